// round 13
// baseline (speedup 1.0000x reference)
#include <cuda_runtime.h>
#include <cuda_bf16.h>
#include <math.h>

#define B_TOT 4096
#define T_LEN 32
#define DDIM 15
#define NSTEPS 5
#define DT_C 0.2f

// GRU mma kernel config (unchanged from R12)
#define GRU_RPB 32
#define GRU_NBLK (B_TOT / GRU_RPB)
#define KS 168
#define KSB 336
#define WOFF 10752
#define GRU_SMEM (10752 + 512 * KSB)

// SDE mma kernel config
#define SDE_RPB 32
#define SDE_NBLK (B_TOT / SDE_RPB)
#define SOFF_ACT0  0         // [32][96] bf16, 192B rows (ctx 64 | sigma 25 | pad 7)
#define SOFF_B1DR  6144      // [32][128] bf16, 256B rows
#define SOFF_B2DR  14336
#define SOFF_B3DR  22528
#define SOFF_B1DF  30720
#define SOFF_B2DF  38912
#define SOFF_W0    47104     // [256][96] bf16 (dr0 | df0)
#define SOFF_W1DR  96256     // [128][128] bf16
#define SOFF_W1DF  129024
#define SOFF_W2DR  161792
#define SOFF_SIG   194560    // [25][33] f32
#define SOFF_CF    197872    // [15][33] f32
#define SOFF_SCR   199856    // [15][33] f32
#define SDE_SMEM   201856

typedef unsigned long long ull;
typedef unsigned int u32;
typedef unsigned short u16;

__device__ __forceinline__ float fsig(float x) { return 1.f / (1.f + __expf(-x)); }
__device__ __forceinline__ float ftanh(float x) { return 1.f - 2.f / (1.f + __expf(2.f * x)); }
__device__ __forceinline__ float bf2f(u16 b) { return __uint_as_float(((u32)b) << 16); }

// ---------------- weight scratch ------------------------------------------------
__device__ float g_dr3T[128 * 15];
__device__ float g_df2T[128 * 15];
__device__ float g_projT[128 * 64];
__device__ float g_ctx[B_TOT * 64];
__device__ __align__(16) u16 g_wmma[512 * KS];      // GRU unified W (R12)
__device__ __align__(16) u16 g_w0[256 * 96];        // SDE L0: dr0 | df0
__device__ __align__(16) u16 g_w1dr[128 * 128];
__device__ __align__(16) u16 g_w1df[128 * 128];
__device__ __align__(16) u16 g_w2dr[128 * 128];

__device__ __forceinline__ u16 bf16u16(float w) {
    __nv_bfloat16 h = __float2bfloat16(w);
    return __bfloat16_as_ushort(h);
}

// ---------------- prep ----------------------------------------------------------
__global__ void prep_kernel(const float* __restrict__ wih, const float* __restrict__ whh,
                            const float* __restrict__ proj,
                            const float* __restrict__ d0, const float* __restrict__ d1,
                            const float* __restrict__ d2, const float* __restrict__ d3,
                            const float* __restrict__ f0, const float* __restrict__ f1,
                            const float* __restrict__ f2) {
    int tid = blockIdx.x * blockDim.x + threadIdx.x;
    int nt = gridDim.x * blockDim.x;

    // GRU unified weight matrix (R12, verified)
    for (int i = tid; i < 512 * KS; i += nt) {
        int j = i / KS, k = i - j * KS;
        int g = j >> 7, jj = j & 127;
        float v = 0.f;
        if (g == 0) {
            if (k < 25) v = wih[jj * 25 + k];
            else if (k >= 32 && k < 160) v = whh[jj * 128 + (k - 32)];
        } else if (g == 1) {
            if (k < 25) v = wih[(128 + jj) * 25 + k];
            else if (k >= 32 && k < 160) v = whh[(128 + jj) * 128 + (k - 32)];
        } else if (g == 2) {
            if (k < 25) v = wih[(256 + jj) * 25 + k];
        } else {
            if (k >= 32 && k < 160) v = whh[(256 + jj) * 128 + (k - 32)];
        }
        g_wmma[i] = bf16u16(v);
    }

    // SDE L0 weights: feature order = ctx(orig 25..88) | sigma(orig 0..24) | pad
    for (int i = tid; i < 256 * 96; i += nt) {
        int j = i / 96, k = i - j * 96;
        const float* W = (j < 128) ? d0 : f0;
        int jj = j & 127;
        float v = 0.f;
        if (k < 64) v = W[jj * 89 + 25 + k];
        else if (k < 89) v = W[jj * 89 + (k - 64)];
        g_w0[i] = bf16u16(v);
    }
    for (int i = tid; i < 128 * 128; i += nt) {
        g_w1dr[i] = bf16u16(d1[i]);
        g_w1df[i] = bf16u16(f1[i]);
        g_w2dr[i] = bf16u16(d2[i]);
    }
    for (int i = tid; i < 15 * 128; i += nt) { int o = i >> 7, k = i & 127; g_dr3T[k * 15 + o] = d3[i]; }
    for (int i = tid; i < 15 * 128; i += nt) { int o = i >> 7, k = i & 127; g_df2T[k * 15 + o] = f2[i]; }
    for (int i = tid; i < 64 * 128; i += nt) { int o = i >> 7, k = i & 127; g_projT[k * 64 + o] = proj[i]; }
}

// ---------------- mma helpers ----------------------------------------------------
__device__ __forceinline__ u32 smem_u32(const void* p) {
    u32 a;
    asm("{ .reg .u64 t; cvta.to.shared.u64 t, %1; cvt.u32.u64 %0, t; }" : "=r"(a) : "l"(p));
    return a;
}

#define LDSM4(R0, R1, R2, R3, ADDR) \
    asm volatile("ldmatrix.sync.aligned.m8n8.x4.shared.b16 {%0,%1,%2,%3}, [%4];" \
        : "=r"(R0), "=r"(R1), "=r"(R2), "=r"(R3) : "r"(ADDR))

#define MMA16816(CACC, B0, B1) \
    asm volatile("mma.sync.aligned.m16n8k16.row.col.f32.bf16.bf16.f32 " \
        "{%0,%1,%2,%3}, {%4,%5,%6,%7}, {%8,%9}, {%0,%1,%2,%3};" \
        : "+f"((CACC)[0]), "+f"((CACC)[1]), "+f"((CACC)[2]), "+f"((CACC)[3]) \
        : "r"(fa0), "r"(fa1), "r"(fa2), "r"(fa3), "r"(B0), "r"(B1))

// ---------------- GRU mma.sync kernel (R12, verified, unchanged) ----------------
__global__ void __launch_bounds__(256, 1)
gru_mma_kernel(const float* __restrict__ C,
               const float* __restrict__ gbias, const float* __restrict__ gbias_n,
               const float* __restrict__ proj_b) {
    extern __shared__ __align__(16) char sm[];
    const u32 smb = smem_u32(sm);

    const int tid = threadIdx.x;
    const int b0 = blockIdx.x * GRU_RPB;
    const int wid = tid >> 5, lane = tid & 31;
    const int rg = wid >> 2;
    const int jq = wid & 3;
    const int j0 = jq * 32;

    {
        const uint4* src = (const uint4*)g_wmma;
        uint4* dst = (uint4*)(sm + WOFF);
        for (int i = tid; i < 10752; i += 256) dst[i] = src[i];
    }
    {
        uint4 z = make_uint4(0, 0, 0, 0);
        uint4* dst = (uint4*)sm;
        for (int i = tid; i < 672; i += 256) dst[i] = z;
    }
    __syncthreads();

    const int rowA = (lane & 7) + ((lane >> 3) & 1) * 8;
    const u32 aBase = smb + (rg * 16 + rowA) * KSB + (((lane >> 4) & 1) * 8) * 2;
    const int rowB = (lane & 7) + ((lane >> 4) & 1) * 8;
    const u32 bBase = smb + WOFF + (j0 + rowB) * KSB + (((lane >> 3) & 1) * 8) * 2;

    float bR[4][2], bZ[4][2], bG[4][2], bN[4][2];
#pragma unroll
    for (int q = 0; q < 4; q++) {
        int j = j0 + q * 8 + (lane & 3) * 2;
        bR[q][0] = gbias[j];        bR[q][1] = gbias[j + 1];
        bZ[q][0] = gbias[128 + j];  bZ[q][1] = gbias[129 + j];
        bG[q][0] = gbias[256 + j];  bG[q][1] = gbias[257 + j];
        bN[q][0] = gbias_n[j];      bN[q][1] = gbias_n[j + 1];
    }

    for (int t = 0; t < T_LEN; t++) {
        for (int i = tid; i < GRU_RPB * 25; i += 256) {
            int r = i / 25, k = i - r * 25;
            int ii = k / 5, jj = k - ii * 5;
            const float* p = C + ((size_t)(b0 + r) * T_LEN + t) * 25;
            float v = 0.5f * (p[ii * 5 + jj] + p[jj * 5 + ii]);
            *(u16*)(sm + r * KSB + k * 2) = bf16u16(v);
        }
        __syncthreads();

        float acc[16][4];
#pragma unroll
        for (int i = 0; i < 16; i++) {
            acc[i][0] = 0.f; acc[i][1] = 0.f; acc[i][2] = 0.f; acc[i][3] = 0.f;
        }
        for (int kt = 0; kt < 10; kt++) {
            u32 fa0, fa1, fa2, fa3;
            LDSM4(fa0, fa1, fa2, fa3, aBase + kt * 32);
#pragma unroll
            for (int g = 0; g < 4; g++) {
#pragma unroll
                for (int p = 0; p < 2; p++) {
                    u32 q0, q1, q2, q3;
                    LDSM4(q0, q1, q2, q3,
                          bBase + (u32)(g * 128 + p * 16) * KSB + kt * 32);
                    MMA16816(acc[g * 4 + 2 * p], q0, q1);
                    MMA16816(acc[g * 4 + 2 * p + 1], q2, q3);
                }
            }
        }

#pragma unroll
        for (int q = 0; q < 4; q++) {
            const float* aR = acc[0 * 4 + q];
            const float* aZ = acc[1 * 4 + q];
            const float* aGI = acc[2 * 4 + q];
            const float* aGH = acc[3 * 4 + q];
            int jc = j0 + q * 8 + (lane & 3) * 2;
#pragma unroll
            for (int half = 0; half < 2; half++) {
                int row = rg * 16 + (lane >> 2) + half * 8;
                u32* hptr = (u32*)(sm + row * KSB + (32 + jc) * 2);
                u32 hold = *hptr;
                float ho0 = bf2f((u16)(hold & 0xFFFFu));
                float ho1 = __uint_as_float(hold & 0xFFFF0000u);
                int c = half * 2;
                float r0 = fsig(aR[c] + bR[q][0]);
                float r1 = fsig(aR[c + 1] + bR[q][1]);
                float z0 = fsig(aZ[c] + bZ[q][0]);
                float z1 = fsig(aZ[c + 1] + bZ[q][1]);
                float g0 = ftanh(aGI[c] + bG[q][0] + r0 * (aGH[c] + bN[q][0]));
                float g1 = ftanh(aGI[c + 1] + bG[q][1] + r1 * (aGH[c + 1] + bN[q][1]));
                float h0 = (1.f - z0) * g0 + z0 * ho0;
                float h1 = (1.f - z1) * g1 + z1 * ho1;
                *hptr = (u32)bf16u16(h0) | ((u32)bf16u16(h1) << 16);
            }
        }
        __syncthreads();
    }

    {
        const int jc = tid & 63, rq = tid >> 6;
        for (int m = 0; m < 8; m++) {
            int r = rq * 8 + m;
            const u16* hrow = (const u16*)(sm + r * KSB + 64);
            float acc = proj_b[jc];
#pragma unroll 4
            for (int k = 0; k < 128; k++) {
                acc += bf2f(hrow[k]) * g_projT[k * 64 + jc];
            }
            g_ctx[(size_t)(b0 + r) * 64 + jc] = acc;
        }
    }
}

// ---------------- geo update (fp32, smem column layout stride 33) ----------------
__device__ __forceinline__ void mm5(const float* A, const float* Bm, float* Cm) {
#pragma unroll
    for (int i = 0; i < 5; i++) {
#pragma unroll
        for (int jj = 0; jj < 5; jj++) {
            float s = A[i * 5] * Bm[jj];
#pragma unroll
            for (int k = 1; k < 5; k++) s += A[i * 5 + k] * Bm[k * 5 + jj];
            Cm[i * 5 + jj] = s;
        }
    }
}

__device__ void geo_sde(float* sig, const float* cf, int e, char* act0) {
    const float is2 = 0.70710678118654752f;
    float S[25];
#pragma unroll
    for (int i = 0; i < 25; i++) S[i] = sig[i * 33 + e];
    float c[15];
#pragma unroll
    for (int i = 0; i < 15; i++) c[i] = cf[i * 33 + e];

    float A[25];
    A[0] = c[0]; A[6] = c[1]; A[12] = c[2]; A[18] = c[3]; A[24] = c[4];
    A[1] = A[5] = c[5] * is2;   A[2] = A[10] = c[6] * is2;
    A[3] = A[15] = c[7] * is2;  A[4] = A[20] = c[8] * is2;
    A[7] = A[11] = c[9] * is2;  A[8] = A[16] = c[10] * is2;
    A[9] = A[21] = c[11] * is2; A[13] = A[17] = c[12] * is2;
    A[14] = A[22] = c[13] * is2; A[19] = A[23] = c[14] * is2;

    float tr = S[0] + S[6] + S[12] + S[18] + S[24];
    float ia = 1.0f / tr;
    float Y[25], Z[25];
#pragma unroll
    for (int i = 0; i < 25; i++) { Y[i] = S[i] * ia; Z[i] = 0.f; }
    Z[0] = Z[6] = Z[12] = Z[18] = Z[24] = 1.f;
    for (int it = 0; it < 12; it++) {
        float P[25]; mm5(Z, Y, P);
        float Tm[25];
#pragma unroll
        for (int i = 0; i < 25; i++) Tm[i] = -0.5f * P[i];
        Tm[0] += 1.5f; Tm[6] += 1.5f; Tm[12] += 1.5f; Tm[18] += 1.5f; Tm[24] += 1.5f;
        float Yn[25], Zn[25];
        mm5(Y, Tm, Yn); mm5(Tm, Z, Zn);
#pragma unroll
        for (int i = 0; i < 25; i++) { Y[i] = Yn[i]; Z[i] = Zn[i]; }
    }
    float sa = sqrtf(tr);
    float L[25];
#pragma unroll
    for (int i = 0; i < 25; i++) L[i] = Y[i] * sa;

    float E[25];
#pragma unroll
    for (int i = 0; i < 25; i++) E[i] = 0.f;
    E[0] = E[6] = E[12] = E[18] = E[24] = 1.f;
#pragma unroll
    for (int k = 8; k >= 1; k--) {
        float AE[25]; mm5(A, E, AE);
        const float invk = 1.0f / (float)k;
#pragma unroll
        for (int i = 0; i < 25; i++) E[i] = AE[i] * invk;
        E[0] += 1.f; E[6] += 1.f; E[12] += 1.f; E[18] += 1.f; E[24] += 1.f;
    }

    float M1[25], M2[25];
    mm5(L, E, M1); mm5(M1, L, M2);
#pragma unroll
    for (int i = 0; i < 5; i++)
#pragma unroll
        for (int jj = 0; jj < 5; jj++) {
            float v = 0.5f * (M2[i * 5 + jj] + M2[jj * 5 + i]);
            sig[(i * 5 + jj) * 33 + e] = v;
            *(u16*)(act0 + e * 192 + (64 + i * 5 + jj) * 2) = bf16u16(v);
        }
}

// ---------------- SDE 128x128 GEMM sub-phase (4-warp team layout) ----------------
// A [32][128] bf16 @ aoff, W [128][128] @ woff, silu -> out [32][128] @ ooff.
// Covers rows rg2*16..+15, cols j0..j0+63.
__device__ __forceinline__ void sde_gemm128(char* sm, u32 smb, int aoff, int woff,
                                            int ooff, int rg2, int j0,
                                            const float* __restrict__ bias, int lane) {
    const int rowA = (lane & 7) + ((lane >> 3) & 1) * 8;
    const u32 aB = smb + aoff + (rg2 * 16 + rowA) * 256 + ((lane >> 4) & 1) * 16;
    const int rowB = (lane & 7) + ((lane >> 4) & 1) * 8;
    const u32 bB = smb + woff + (j0 + rowB) * 256 + ((lane >> 3) & 1) * 16;

    float acc[8][4];
#pragma unroll
    for (int i = 0; i < 8; i++) { acc[i][0] = acc[i][1] = acc[i][2] = acc[i][3] = 0.f; }
#pragma unroll
    for (int kt = 0; kt < 8; kt++) {
        u32 fa0, fa1, fa2, fa3;
        LDSM4(fa0, fa1, fa2, fa3, aB + kt * 32);
#pragma unroll
        for (int p = 0; p < 4; p++) {
            u32 q0, q1, q2, q3;
            LDSM4(q0, q1, q2, q3, bB + (u32)(p * 16) * 256 + kt * 32);
            MMA16816(acc[2 * p], q0, q1);
            MMA16816(acc[2 * p + 1], q2, q3);
        }
    }
#pragma unroll
    for (int t = 0; t < 8; t++) {
        int jc = j0 + t * 8 + (lane & 3) * 2;
        float bb0 = bias[jc], bb1 = bias[jc + 1];
#pragma unroll
        for (int half = 0; half < 2; half++) {
            int row = rg2 * 16 + (lane >> 2) + half * 8;
            float x0 = acc[t][half * 2] + bb0;
            float x1 = acc[t][half * 2 + 1] + bb1;
            float s0 = x0 * fsig(x0), s1 = x1 * fsig(x1);
            *(u32*)(sm + ooff + row * 256 + jc * 2) =
                (u32)bf16u16(s0) | ((u32)bf16u16(s1) << 16);
        }
    }
}

// ---------------- SDE mma kernel: 128 CTAs x 256 thr, 32 rows --------------------
__global__ void __launch_bounds__(256, 1)
sde_mma_kernel(const float* __restrict__ C, const float* __restrict__ dW,
               const float* __restrict__ pdb0, const float* __restrict__ pdb1,
               const float* __restrict__ pdb2, const float* __restrict__ pdb3,
               const float* __restrict__ pfb0, const float* __restrict__ pfb1,
               const float* __restrict__ pfb2, float* __restrict__ out) {
    extern __shared__ __align__(16) char sm[];
    const u32 smb = smem_u32(sm);
    float* sig = (float*)(sm + SOFF_SIG);
    float* cf  = (float*)(sm + SOFF_CF);
    float* scr = (float*)(sm + SOFF_SCR);

    const int tid = threadIdx.x;
    const int b0 = blockIdx.x * SDE_RPB;
    const int wid = tid >> 5, lane = tid & 31;

    // stage weights: W0 3072 + 3 x 2048 uint4
    {
        uint4* dst = (uint4*)(sm + SOFF_W0);
        const uint4* src = (const uint4*)g_w0;
        for (int i = tid; i < 3072; i += 256) dst[i] = src[i];
        dst = (uint4*)(sm + SOFF_W1DR); src = (const uint4*)g_w1dr;
        for (int i = tid; i < 2048; i += 256) dst[i] = src[i];
        dst = (uint4*)(sm + SOFF_W1DF); src = (const uint4*)g_w1df;
        for (int i = tid; i < 2048; i += 256) dst[i] = src[i];
        dst = (uint4*)(sm + SOFF_W2DR); src = (const uint4*)g_w2dr;
        for (int i = tid; i < 2048; i += 256) dst[i] = src[i];
    }
    // zero ACT0 (32*96 u16 = 1536 u32)
    for (int i = tid; i < 1536; i += 256) ((u32*)(sm + SOFF_ACT0))[i] = 0u;
    __syncthreads();
    // stage ctx cols 0..63
    for (int i = tid; i < SDE_RPB * 64; i += 256) {
        int r = i >> 6, k = i & 63;
        *(u16*)(sm + SOFF_ACT0 + r * 192 + k * 2) = bf16u16(g_ctx[(size_t)(b0 + r) * 64 + k]);
    }
    // sigma_0: fp32 to sig + bf16 to ACT0 cols 64..88
    for (int i = tid; i < SDE_RPB * 25; i += 256) {
        int r = i / 25, k = i - r * 25;
        int ii = k / 5, jj = k - ii * 5;
        const float* p = C + ((size_t)(b0 + r) * T_LEN + (T_LEN - 1)) * 25;
        float v = 0.5f * (p[ii * 5 + jj] + p[jj * 5 + ii]);
        sig[k * 33 + r] = v;
        *(u16*)(sm + SOFF_ACT0 + r * 192 + (64 + k) * 2) = bf16u16(v);
    }
    __syncthreads();

    const int rg = wid >> 2, jq = wid & 3;

    for (int step = 0; step < NSTEPS; step++) {
        // ===== P1: L0 (N=256 = dr0 | df0), K=96, all 8 warps =====
        {
            const int rowA = (lane & 7) + ((lane >> 3) & 1) * 8;
            const u32 aB = smb + SOFF_ACT0 + (rg * 16 + rowA) * 192 + ((lane >> 4) & 1) * 16;
            const int rowB = (lane & 7) + ((lane >> 4) & 1) * 8;
            const u32 bB = smb + SOFF_W0 + (jq * 64 + rowB) * 192 + ((lane >> 3) & 1) * 16;
            float acc[8][4];
#pragma unroll
            for (int i = 0; i < 8; i++) { acc[i][0] = acc[i][1] = acc[i][2] = acc[i][3] = 0.f; }
#pragma unroll
            for (int kt = 0; kt < 6; kt++) {
                u32 fa0, fa1, fa2, fa3;
                LDSM4(fa0, fa1, fa2, fa3, aB + kt * 32);
#pragma unroll
                for (int p = 0; p < 4; p++) {
                    u32 q0, q1, q2, q3;
                    LDSM4(q0, q1, q2, q3, bB + (u32)(p * 16) * 192 + kt * 32);
                    MMA16816(acc[2 * p], q0, q1);
                    MMA16816(acc[2 * p + 1], q2, q3);
                }
            }
#pragma unroll
            for (int t = 0; t < 8; t++) {
                int jg = jq * 64 + t * 8 + (lane & 3) * 2;
                int jl = jg & 127;
                const float* bias = (jg < 128) ? pdb0 : pfb0;
                int ooff = (jg < 128) ? SOFF_B1DR : SOFF_B1DF;
                float bb0 = bias[jl], bb1 = bias[jl + 1];
#pragma unroll
                for (int half = 0; half < 2; half++) {
                    int row = rg * 16 + (lane >> 2) + half * 8;
                    float x0 = acc[t][half * 2] + bb0;
                    float x1 = acc[t][half * 2 + 1] + bb1;
                    float s0 = x0 * fsig(x0), s1 = x1 * fsig(x1);
                    *(u32*)(sm + ooff + row * 256 + jl * 2) =
                        (u32)bf16u16(s0) | ((u32)bf16u16(s1) << 16);
                }
            }
        }
        __syncthreads();

        // ===== P2: L1 (drift: warps 0-3; diff: warps 4-7) =====
        {
            int chain = wid >> 2;
            int rg2 = (wid >> 1) & 1, jh = wid & 1;
            int aoff = chain ? SOFF_B1DF : SOFF_B1DR;
            int woff = chain ? SOFF_W1DF : SOFF_W1DR;
            int ooff = chain ? SOFF_B2DF : SOFF_B2DR;
            const float* bias = chain ? pfb1 : pdb1;
            sde_gemm128(sm, smb, aoff, woff, ooff, rg2, jh * 64, bias, lane);
        }
        __syncthreads();

        // ===== P3: drift L2 mma (warps 0-3) || diff L2out scalar (warps 4-7) =====
        if (wid < 4) {
            sde_gemm128(sm, smb, SOFF_B2DR, SOFF_W2DR, SOFF_B3DR,
                        wid >> 1, (wid & 1) * 64, pdb2, lane);
        } else {
            int w = tid - 128;
            for (int i = w; i < SDE_RPB * 15; i += 128) {
                int r = i / 15, k = i - r * 15;
                float acc = pfb2[k];
                const u32* arow = (const u32*)(sm + SOFF_B2DF + r * 256);
#pragma unroll 4
                for (int c2 = 0; c2 < 64; c2++) {
                    u32 pr = arow[c2];
                    acc += bf2f((u16)(pr & 0xFFFFu)) * g_df2T[(2 * c2) * 15 + k];
                    acc += __uint_as_float(pr & 0xFFFF0000u) * g_df2T[(2 * c2 + 1) * 15 + k];
                }
                scr[k * 33 + r] = acc;
            }
        }
        __syncthreads();

        // ===== P4: drift L3 scalar + coeff combine =====
        for (int i = tid; i < SDE_RPB * 15; i += 256) {
            int r = i / 15, k = i - r * 15;
            float acc = pdb3[k];
            const u32* arow = (const u32*)(sm + SOFF_B3DR + r * 256);
#pragma unroll 4
            for (int c2 = 0; c2 < 64; c2++) {
                u32 pr = arow[c2];
                acc += bf2f((u16)(pr & 0xFFFFu)) * g_dr3T[(2 * c2) * 15 + k];
                acc += __uint_as_float(pr & 0xFFFF0000u) * g_dr3T[(2 * c2 + 1) * 15 + k];
            }
            float raw = scr[k * 33 + r];
            float sp = (raw > 20.f) ? raw : log1pf(__expf(raw));
            float dwv = dW[((size_t)(b0 + r) * NSTEPS + step) * DDIM + k];
            cf[k * 33 + r] = acc * DT_C + sp * dwv;
        }
        __syncthreads();

        // ===== P5: geometric update (32 lanes of warp 0) =====
        if (tid < SDE_RPB) geo_sde(sig, cf, tid, sm + SOFF_ACT0);
        __syncthreads();
    }

    for (int i = tid; i < SDE_RPB * 25; i += 256) {
        int r = i / 25, k = i - r * 25;
        out[(size_t)(b0 + r) * 25 + k] = sig[k * 33 + r];
    }
}

// ---------------- launch ---------------------------------------------------------
extern "C" void kernel_launch(void* const* d_in, const int* in_sizes, int n_in,
                              void* d_out, int out_size) {
    const float* ctx_spd = (const float*)d_in[0];
    const float* dWp     = (const float*)d_in[1];
    const float* wih     = (const float*)d_in[2];
    const float* whh     = (const float*)d_in[3];
    const float* gbias   = (const float*)d_in[4];
    const float* gbias_n = (const float*)d_in[5];
    const float* projw   = (const float*)d_in[6];
    const float* projb   = (const float*)d_in[7];
    const float* dw0 = (const float*)d_in[8];  const float* db0 = (const float*)d_in[9];
    const float* dw1 = (const float*)d_in[10]; const float* db1 = (const float*)d_in[11];
    const float* dw2 = (const float*)d_in[12]; const float* db2 = (const float*)d_in[13];
    const float* dw3 = (const float*)d_in[14]; const float* db3 = (const float*)d_in[15];
    const float* fw0 = (const float*)d_in[16]; const float* fb0 = (const float*)d_in[17];
    const float* fw1 = (const float*)d_in[18]; const float* fb1 = (const float*)d_in[19];
    const float* fw2 = (const float*)d_in[20]; const float* fb2 = (const float*)d_in[21];
    float* out = (float*)d_out;

    static int smem_set = 0;
    if (!smem_set) {
        cudaFuncSetAttribute(gru_mma_kernel, cudaFuncAttributeMaxDynamicSharedMemorySize, GRU_SMEM);
        cudaFuncSetAttribute(sde_mma_kernel, cudaFuncAttributeMaxDynamicSharedMemorySize, SDE_SMEM);
        smem_set = 1;
    }

    prep_kernel<<<64, 256>>>(wih, whh, projw, dw0, dw1, dw2, dw3, fw0, fw1, fw2);
    gru_mma_kernel<<<GRU_NBLK, 256, GRU_SMEM>>>(ctx_spd, gbias, gbias_n, projb);
    sde_mma_kernel<<<SDE_NBLK, 256, SDE_SMEM>>>(ctx_spd, dWp, db0, db1, db2, db3,
                                                fb0, fb1, fb2, out);
}

// round 14
// speedup vs baseline: 1.4484x; 1.4484x over previous
#include <cuda_runtime.h>
#include <cuda_bf16.h>
#include <math.h>

#define B_TOT 4096
#define T_LEN 32
#define DDIM 15
#define NSTEPS 5
#define DT_C 0.2f
#define RPB 16
#define NBLK (B_TOT / RPB)
#define PAD 20

// GRU mma kernel config
#define GRU_RPB 32
#define GRU_NBLK (B_TOT / GRU_RPB)
#define KS 168
#define KSB 336
#define WOFF 10752
#define GRU_SMEM (10752 + 512 * KSB)

typedef unsigned long long ull;
typedef unsigned int u32;
typedef unsigned short u16;

__device__ __forceinline__ float tanhapx(float x) {
    float y; asm("tanh.approx.f32 %0, %1;" : "=f"(y) : "f"(x)); return y;
}
__device__ __forceinline__ float fsig(float x) { return fmaf(0.5f, tanhapx(0.5f * x), 0.5f); }
__device__ __forceinline__ float ftanh(float x) { return tanhapx(x); }
__device__ __forceinline__ float bf2f(u16 b) { return __uint_as_float(((u32)b) << 16); }

// ---------------- packed f32x2 helpers (SDE path) --------------------------------
__device__ __forceinline__ void fma2(ull& acc, ull a, ull b) {
    asm("fma.rn.f32x2 %0, %1, %2, %0;" : "+l"(acc) : "l"(a), "l"(b));
}
__device__ __forceinline__ ull pack2f(float w) {
    ull r; asm("mov.b64 %0, {%1, %1};" : "=l"(r) : "r"(__float_as_uint(w))); return r;
}
__device__ __forceinline__ ull bplo(u32 u) {
    u32 f = u << 16; ull r; asm("mov.b64 %0, {%1, %1};" : "=l"(r) : "r"(f)); return r;
}
__device__ __forceinline__ ull bphi(u32 u) {
    u32 f = u & 0xFFFF0000u; ull r; asm("mov.b64 %0, {%1, %1};" : "=l"(r) : "r"(f)); return r;
}
__device__ __forceinline__ float2 unpack2(ull v) {
    float2 f; asm("mov.b64 {%0, %1}, %2;" : "=f"(f.x), "=f"(f.y) : "l"(v)); return f;
}

// ---------------- weight scratch ------------------------------------------------
__device__ __align__(16) u32 g_dr0C[4096];
__device__ __align__(16) u32 g_df0C[4096];
__device__ __align__(16) u32 g_dr0D[2048];
__device__ __align__(16) u32 g_df0D[2048];
__device__ __align__(16) u32 g_dr1P[8192];
__device__ __align__(16) u32 g_dr2P[8192];
__device__ __align__(16) u32 g_df1P[8192];
__device__ float g_dr3T[128 * 15];
__device__ float g_df2T[128 * 15];
__device__ float g_projT[128 * 64];
__device__ float g_ctx[B_TOT * 64];
// GRU gate-interleaved weight matrix W'[512][KS] bf16:
//   row n = chunk*64 + gate*16 + jr, j = chunk*16 + jr
//   gate 0: r (ih k<25, hh 32<=k<160); 1: z (same); 2: gi (ih only); 3: gh (hh only)
__device__ __align__(16) u16 g_wmma[512 * KS];

__device__ __forceinline__ u32 bfbits(float w) {
    __nv_bfloat16 h = __float2bfloat16(w);
    return (u32)__bfloat16_as_ushort(h);
}
__device__ __forceinline__ u16 bf16u16(float w) {
    __nv_bfloat16 h = __float2bfloat16(w);
    return __bfloat16_as_ushort(h);
}

// ---------------- prep ----------------------------------------------------------
__global__ void prep_kernel(const float* __restrict__ wih, const float* __restrict__ whh,
                            const float* __restrict__ proj,
                            const float* __restrict__ d0, const float* __restrict__ d1,
                            const float* __restrict__ d2, const float* __restrict__ d3,
                            const float* __restrict__ f0, const float* __restrict__ f1,
                            const float* __restrict__ f2) {
    int tid = blockIdx.x * blockDim.x + threadIdx.x;
    int nt = gridDim.x * blockDim.x;

    // GRU gate-interleaved weight matrix
    for (int i = tid; i < 512 * KS; i += nt) {
        int n = i / KS, k = i - n * KS;
        int chunk = n >> 6, rem = n & 63, gate = rem >> 4, jr = rem & 15;
        int j = chunk * 16 + jr;
        float v = 0.f;
        if (gate == 0) {
            if (k < 25) v = wih[j * 25 + k];
            else if (k >= 32 && k < 160) v = whh[j * 128 + (k - 32)];
        } else if (gate == 1) {
            if (k < 25) v = wih[(128 + j) * 25 + k];
            else if (k >= 32 && k < 160) v = whh[(128 + j) * 128 + (k - 32)];
        } else if (gate == 2) {
            if (k < 25) v = wih[(256 + j) * 25 + k];
        } else {
            if (k >= 32 && k < 160) v = whh[(256 + j) * 128 + (k - 32)];
        }
        g_wmma[i] = bf16u16(v);
    }

    // ---- SDE weights (proven R9/R12 packing) ----
    for (int i = tid; i < 4096; i += nt) {
        int t = i & 3, j = (i >> 2) & 127, kb = i >> 9;
        int kp = kb * 4 + t;
        g_dr0C[i] = bfbits(d0[j * 89 + 25 + 2 * kp]) | (bfbits(d0[j * 89 + 26 + 2 * kp]) << 16);
        g_df0C[i] = bfbits(f0[j * 89 + 25 + 2 * kp]) | (bfbits(f0[j * 89 + 26 + 2 * kp]) << 16);
    }
    for (int i = tid; i < 2048; i += nt) {
        int t = i & 3, j = (i >> 2) & 127, kb = i >> 9;
        int kp = kb * 4 + t, k0 = 2 * kp, k1 = 2 * kp + 1;
        float a0 = (k0 < 25) ? d0[j * 89 + k0] : 0.f;
        float a1 = (k1 < 25) ? d0[j * 89 + k1] : 0.f;
        g_dr0D[i] = bfbits(a0) | (bfbits(a1) << 16);
        float c0 = (k0 < 25) ? f0[j * 89 + k0] : 0.f;
        float c1 = (k1 < 25) ? f0[j * 89 + k1] : 0.f;
        g_df0D[i] = bfbits(c0) | (bfbits(c1) << 16);
    }
    for (int i = tid; i < 8192; i += nt) {
        int t = i & 3, j = (i >> 2) & 127, kb = i >> 9;
        int kp = kb * 4 + t;
        g_dr1P[i] = bfbits(d1[j * 128 + 2 * kp]) | (bfbits(d1[j * 128 + 2 * kp + 1]) << 16);
        g_dr2P[i] = bfbits(d2[j * 128 + 2 * kp]) | (bfbits(d2[j * 128 + 2 * kp + 1]) << 16);
        g_df1P[i] = bfbits(f1[j * 128 + 2 * kp]) | (bfbits(f1[j * 128 + 2 * kp + 1]) << 16);
    }
    for (int i = tid; i < 15 * 128; i += nt) { int o = i >> 7, k = i & 127; g_dr3T[k * 15 + o] = d3[i]; }
    for (int i = tid; i < 15 * 128; i += nt) { int o = i >> 7, k = i & 127; g_df2T[k * 15 + o] = f2[i]; }
    for (int i = tid; i < 64 * 128; i += nt) { int o = i >> 7, k = i & 127; g_projT[k * 64 + o] = proj[i]; }
}

// ---------------- mma helpers ----------------------------------------------------
__device__ __forceinline__ u32 smem_u32(const void* p) {
    u32 a;
    asm("{ .reg .u64 t; cvta.to.shared.u64 t, %1; cvt.u32.u64 %0, t; }" : "=r"(a) : "l"(p));
    return a;
}

#define LDSM4(R0, R1, R2, R3, ADDR) \
    asm volatile("ldmatrix.sync.aligned.m8n8.x4.shared.b16 {%0,%1,%2,%3}, [%4];" \
        : "=r"(R0), "=r"(R1), "=r"(R2), "=r"(R3) : "r"(ADDR))

#define MMAF(CACC, A0, A1, A2, A3, B0, B1) \
    asm volatile("mma.sync.aligned.m16n8k16.row.col.f32.bf16.bf16.f32 " \
        "{%0,%1,%2,%3}, {%4,%5,%6,%7}, {%8,%9}, {%0,%1,%2,%3};" \
        : "+f"((CACC)[0]), "+f"((CACC)[1]), "+f"((CACC)[2]), "+f"((CACC)[3]) \
        : "r"(A0), "r"(A1), "r"(A2), "r"(A3), "r"(B0), "r"(B1))

// ---------------- GRU mma.sync kernel: 128 CTAs x 256 thr, 32 rows --------------
// New tiling: warp w owns ALL 32 rows x 16 j-columns (all 4 gates interleaved).
__global__ void __launch_bounds__(256, 1)
gru_mma_kernel(const float* __restrict__ C,
               const float* __restrict__ gbias, const float* __restrict__ gbias_n,
               const float* __restrict__ proj_b) {
    extern __shared__ __align__(16) char sm[];
    const u32 smb = smem_u32(sm);

    const int tid = threadIdx.x;
    const int b0 = blockIdx.x * GRU_RPB;
    const int wid = tid >> 5, lane = tid & 31;
    const int w16 = wid * 16;

    {
        const uint4* src = (const uint4*)g_wmma;
        uint4* dst = (uint4*)(sm + WOFF);
        for (int i = tid; i < 10752; i += 256) dst[i] = src[i];
    }
    {
        uint4 z = make_uint4(0, 0, 0, 0);
        uint4* dst = (uint4*)sm;
        for (int i = tid; i < 672; i += 256) dst[i] = z;
    }
    __syncthreads();

    // A ldmatrix bases (2 m-tiles of 16 rows)
    const int rowA = (lane & 7) + ((lane >> 3) & 1) * 8;
    const u32 aB0 = smb + rowA * KSB + (((lane >> 4) & 1) * 8) * 2;
    const u32 aB1 = aB0 + 16 * KSB;
    // B ldmatrix base: rows w*64 + gate*16 + rowB
    const int rowB = (lane & 7) + ((lane >> 4) & 1) * 8;
    const u32 bB = smb + WOFF + (wid * 64 + rowB) * KSB + (((lane >> 3) & 1) * 8) * 2;

    // biases for this thread's j values: j = w16 + q*8 + (lane&3)*2
    float bR[2][2], bZ[2][2], bG[2][2], bN[2][2];
#pragma unroll
    for (int q = 0; q < 2; q++) {
        int j = w16 + q * 8 + (lane & 3) * 2;
        bR[q][0] = gbias[j];        bR[q][1] = gbias[j + 1];
        bZ[q][0] = gbias[128 + j];  bZ[q][1] = gbias[129 + j];
        bG[q][0] = gbias[256 + j];  bG[q][1] = gbias[257 + j];
        bN[q][0] = gbias_n[j];      bN[q][1] = gbias_n[j + 1];
    }

    for (int t = 0; t < T_LEN; t++) {
        // stage X_t (sym, bf16) into A[m][k<25]
        for (int i = tid; i < GRU_RPB * 25; i += 256) {
            int r = i / 25, k = i - r * 25;
            int ii = k / 5, jj = k - ii * 5;
            const float* p = C + ((size_t)(b0 + r) * T_LEN + t) * 25;
            float v = 0.5f * (p[ii * 5 + jj] + p[jj * 5 + ii]);
            *(u16*)(sm + r * KSB + k * 2) = bf16u16(v);
        }
        __syncthreads();

        // acc[mi][gate][q][c]
        float acc[2][4][2][4];
#pragma unroll
        for (int mi = 0; mi < 2; mi++)
#pragma unroll
            for (int g = 0; g < 4; g++)
#pragma unroll
                for (int q = 0; q < 2; q++) {
                    acc[mi][g][q][0] = 0.f; acc[mi][g][q][1] = 0.f;
                    acc[mi][g][q][2] = 0.f; acc[mi][g][q][3] = 0.f;
                }

#pragma unroll
        for (int kt = 0; kt < 10; kt++) {
            u32 fa0[4], fa1[4];
            LDSM4(fa0[0], fa0[1], fa0[2], fa0[3], aB0 + kt * 32);
            LDSM4(fa1[0], fa1[1], fa1[2], fa1[3], aB1 + kt * 32);
            // r gate (0): all kt
            {
                u32 q0, q1, q2, q3;
                LDSM4(q0, q1, q2, q3, bB + kt * 32);
                MMAF(acc[0][0][0], fa0[0], fa0[1], fa0[2], fa0[3], q0, q1);
                MMAF(acc[0][0][1], fa0[0], fa0[1], fa0[2], fa0[3], q2, q3);
                MMAF(acc[1][0][0], fa1[0], fa1[1], fa1[2], fa1[3], q0, q1);
                MMAF(acc[1][0][1], fa1[0], fa1[1], fa1[2], fa1[3], q2, q3);
            }
            // z gate (1): all kt
            {
                u32 q0, q1, q2, q3;
                LDSM4(q0, q1, q2, q3, bB + 16 * KSB + kt * 32);
                MMAF(acc[0][1][0], fa0[0], fa0[1], fa0[2], fa0[3], q0, q1);
                MMAF(acc[0][1][1], fa0[0], fa0[1], fa0[2], fa0[3], q2, q3);
                MMAF(acc[1][1][0], fa1[0], fa1[1], fa1[2], fa1[3], q0, q1);
                MMAF(acc[1][1][1], fa1[0], fa1[1], fa1[2], fa1[3], q2, q3);
            }
            // gi (2) only kt<2 (x cols); gh (3) only kt>=2 (h cols)
            {
                int g = (kt < 2) ? 2 : 3;
                u32 q0, q1, q2, q3;
                LDSM4(q0, q1, q2, q3, bB + g * 16 * KSB + kt * 32);
                MMAF(acc[0][g][0], fa0[0], fa0[1], fa0[2], fa0[3], q0, q1);
                MMAF(acc[0][g][1], fa0[0], fa0[1], fa0[2], fa0[3], q2, q3);
                MMAF(acc[1][g][0], fa1[0], fa1[1], fa1[2], fa1[3], q0, q1);
                MMAF(acc[1][g][1], fa1[0], fa1[1], fa1[2], fa1[3], q2, q3);
            }
        }

        // epilogue: gates + h update
#pragma unroll
        for (int mi = 0; mi < 2; mi++) {
#pragma unroll
            for (int q = 0; q < 2; q++) {
                int jc = w16 + q * 8 + (lane & 3) * 2;
                const float* aR = acc[mi][0][q];
                const float* aZ = acc[mi][1][q];
                const float* aGI = acc[mi][2][q];
                const float* aGH = acc[mi][3][q];
#pragma unroll
                for (int half = 0; half < 2; half++) {
                    int row = mi * 16 + (lane >> 2) + half * 8;
                    u32* hptr = (u32*)(sm + row * KSB + (32 + jc) * 2);
                    u32 hold = *hptr;
                    float ho0 = bf2f((u16)(hold & 0xFFFFu));
                    float ho1 = __uint_as_float(hold & 0xFFFF0000u);
                    int c = half * 2;
                    float r0 = fsig(aR[c] + bR[q][0]);
                    float r1 = fsig(aR[c + 1] + bR[q][1]);
                    float z0 = fsig(aZ[c] + bZ[q][0]);
                    float z1 = fsig(aZ[c + 1] + bZ[q][1]);
                    float g0 = ftanh(aGI[c] + bG[q][0] + r0 * (aGH[c] + bN[q][0]));
                    float g1 = ftanh(aGI[c + 1] + bG[q][1] + r1 * (aGH[c + 1] + bN[q][1]));
                    float h0 = (1.f - z0) * g0 + z0 * ho0;
                    float h1 = (1.f - z1) * g1 + z1 * ho1;
                    *hptr = (u32)bf16u16(h0) | ((u32)bf16u16(h1) << 16);
                }
            }
        }
        __syncthreads();
    }

    // projection: ctx = h @ proj^T + proj_b -> g_ctx
    {
        const int jc = tid & 63, rq = tid >> 6;
        for (int m = 0; m < 8; m++) {
            int r = rq * 8 + m;
            const u16* hrow = (const u16*)(sm + r * KSB + 64);
            float acc = proj_b[jc];
#pragma unroll 4
            for (int k = 0; k < 128; k++) {
                acc += bf2f(hrow[k]) * g_projT[k * 64 + jc];
            }
            g_ctx[(size_t)(b0 + r) * 64 + jc] = acc;
        }
    }
}

// ---------------- 5x5 helpers ----------------------------------------------------
__device__ __forceinline__ void mm5(const float* A, const float* Bm, float* Cm) {
#pragma unroll
    for (int i = 0; i < 5; i++) {
#pragma unroll
        for (int jj = 0; jj < 5; jj++) {
            float s = A[i * 5] * Bm[jj];
#pragma unroll
            for (int k = 1; k < 5; k++) s += A[i * 5 + k] * Bm[k * 5 + jj];
            Cm[i * 5 + jj] = s;
        }
    }
}

__device__ void geo_update(float* base) {
    const float is2 = 0.70710678118654752f;
    float S[25];
#pragma unroll
    for (int i = 0; i < 25; i++) S[i] = base[(64 + i) * PAD];
    float c[15];
#pragma unroll
    for (int i = 0; i < 15; i++) c[i] = base[(90 + i) * PAD];

    float A[25];
    A[0] = c[0]; A[6] = c[1]; A[12] = c[2]; A[18] = c[3]; A[24] = c[4];
    A[1] = A[5] = c[5] * is2;   A[2] = A[10] = c[6] * is2;
    A[3] = A[15] = c[7] * is2;  A[4] = A[20] = c[8] * is2;
    A[7] = A[11] = c[9] * is2;  A[8] = A[16] = c[10] * is2;
    A[9] = A[21] = c[11] * is2; A[13] = A[17] = c[12] * is2;
    A[14] = A[22] = c[13] * is2; A[19] = A[23] = c[14] * is2;

    float tr = S[0] + S[6] + S[12] + S[18] + S[24];
    float ia = 1.0f / tr;
    float Y[25], Z[25];
#pragma unroll
    for (int i = 0; i < 25; i++) { Y[i] = S[i] * ia; Z[i] = 0.f; }
    Z[0] = Z[6] = Z[12] = Z[18] = Z[24] = 1.f;
    for (int it = 0; it < 12; it++) {
        float P[25]; mm5(Z, Y, P);
        float Tm[25];
#pragma unroll
        for (int i = 0; i < 25; i++) Tm[i] = -0.5f * P[i];
        Tm[0] += 1.5f; Tm[6] += 1.5f; Tm[12] += 1.5f; Tm[18] += 1.5f; Tm[24] += 1.5f;
        float Yn[25], Zn[25];
        mm5(Y, Tm, Yn); mm5(Tm, Z, Zn);
#pragma unroll
        for (int i = 0; i < 25; i++) { Y[i] = Yn[i]; Z[i] = Zn[i]; }
    }
    float sa = sqrtf(tr);
    float L[25];
#pragma unroll
    for (int i = 0; i < 25; i++) L[i] = Y[i] * sa;

    float E[25];
#pragma unroll
    for (int i = 0; i < 25; i++) E[i] = 0.f;
    E[0] = E[6] = E[12] = E[18] = E[24] = 1.f;
#pragma unroll
    for (int k = 8; k >= 1; k--) {
        float AE[25]; mm5(A, E, AE);
        const float invk = 1.0f / (float)k;
#pragma unroll
        for (int i = 0; i < 25; i++) E[i] = AE[i] * invk;
        E[0] += 1.f; E[6] += 1.f; E[12] += 1.f; E[18] += 1.f; E[24] += 1.f;
    }

    float M1[25], M2[25];
    mm5(L, E, M1); mm5(M1, L, M2);
#pragma unroll
    for (int i = 0; i < 5; i++)
#pragma unroll
        for (int jj = 0; jj < 5; jj++)
            base[(64 + i * 5 + jj) * PAD] = 0.5f * (M2[i * 5 + jj] + M2[jj * 5 + i]);
}

// ---------------- SDE pair macros (R9/R12) ---------------------------------------
#define MLP_PAIR(WW, IN, KK) do { \
    ull w0 = bplo(WW), w1 = bphi(WW); \
    ulonglong2 v0 = *(const ulonglong2*)&IN[KK][rbase]; \
    ulonglong2 v1 = *(const ulonglong2*)&IN[KK][rbase + 4]; \
    ulonglong2 u0 = *(const ulonglong2*)&IN[KK + 1][rbase]; \
    ulonglong2 u1 = *(const ulonglong2*)&IN[KK + 1][rbase + 4]; \
    fma2(acc[0], w0, v0.x); fma2(acc[1], w0, v0.y); fma2(acc[2], w0, v1.x); fma2(acc[3], w0, v1.y); \
    fma2(acc[0], w1, u0.x); fma2(acc[1], w1, u0.y); fma2(acc[2], w1, u1.x); fma2(acc[3], w1, u1.y); \
} while (0)

#define CTX_PAIR(WD, WF, KK) do { \
    ull d0w = bplo(WD), d1w = bphi(WD); \
    ull f0w = bplo(WF), f1w = bphi(WF); \
    ulonglong2 v0 = *(const ulonglong2*)&inp_s[KK][rbase]; \
    ulonglong2 v1 = *(const ulonglong2*)&inp_s[KK][rbase + 4]; \
    ulonglong2 u0 = *(const ulonglong2*)&inp_s[KK + 1][rbase]; \
    ulonglong2 u1 = *(const ulonglong2*)&inp_s[KK + 1][rbase + 4]; \
    fma2(pc_dr[0], d0w, v0.x); fma2(pc_dr[1], d0w, v0.y); fma2(pc_dr[2], d0w, v1.x); fma2(pc_dr[3], d0w, v1.y); \
    fma2(pc_dr[0], d1w, u0.x); fma2(pc_dr[1], d1w, u0.y); fma2(pc_dr[2], d1w, u1.x); fma2(pc_dr[3], d1w, u1.y); \
    fma2(pc_df[0], f0w, v0.x); fma2(pc_df[1], f0w, v0.y); fma2(pc_df[2], f0w, v1.x); fma2(pc_df[3], f0w, v1.y); \
    fma2(pc_df[0], f1w, u0.x); fma2(pc_df[1], f1w, u0.y); fma2(pc_df[2], f1w, u1.x); fma2(pc_df[3], f1w, u1.y); \
} while (0)

__device__ __forceinline__ void mlp_layer64(const u32* __restrict__ Wp,
                                            const float (*in_s)[PAD], float (*out_s)[PAD],
                                            float bias, int j, int rbase) {
    ull acc[4];
    ull b2 = pack2f(bias);
#pragma unroll
    for (int p = 0; p < 4; p++) acc[p] = b2;
#pragma unroll 4
    for (int kb = 0; kb < 16; kb++) {
        uint4 w4 = ((const uint4*)Wp)[kb * 128 + j];
        int k = kb * 8;
        MLP_PAIR(w4.x, in_s, k);
        MLP_PAIR(w4.y, in_s, k + 2);
        MLP_PAIR(w4.z, in_s, k + 4);
        MLP_PAIR(w4.w, in_s, k + 6);
    }
#pragma unroll
    for (int p = 0; p < 4; p++) {
        float2 f = unpack2(acc[p]);
        out_s[j][rbase + 2 * p] = f.x * fsig(f.x);
        out_s[j][rbase + 2 * p + 1] = f.y * fsig(f.y);
    }
}

__device__ __forceinline__ void mlp_layer0(const u32* __restrict__ Wp,
                                           const float (*in_s)[PAD], float (*out_s)[PAD],
                                           const ull* pc, int j, int rbase) {
    ull acc[4];
#pragma unroll
    for (int p = 0; p < 4; p++) acc[p] = pc[p];
#pragma unroll
    for (int kb = 0; kb < 4; kb++) {
        uint4 w4 = ((const uint4*)Wp)[kb * 128 + j];
        int k = 64 + kb * 8;
        MLP_PAIR(w4.x, in_s, k);
        MLP_PAIR(w4.y, in_s, k + 2);
        MLP_PAIR(w4.z, in_s, k + 4);
        MLP_PAIR(w4.w, in_s, k + 6);
    }
#pragma unroll
    for (int p = 0; p < 4; p++) {
        float2 f = unpack2(acc[p]);
        out_s[j][rbase + 2 * p] = f.x * fsig(f.x);
        out_s[j][rbase + 2 * p + 1] = f.y * fsig(f.y);
    }
}

// ---------------- SDE scalar kernel (R12, ctx from g_ctx) ------------------------
__global__ void __launch_bounds__(256, 2) sde_kernel(
    const float* __restrict__ C, const float* __restrict__ dW,
    const float* __restrict__ db0, const float* __restrict__ db1,
    const float* __restrict__ db2, const float* __restrict__ db3,
    const float* __restrict__ fb0, const float* __restrict__ fb1,
    const float* __restrict__ fb2, float* __restrict__ out) {
    __shared__ __align__(16) float pool_s[5120];
    __shared__ __align__(16) float inp_s[106][PAD];

    float (*b1_s)[PAD] = (float (*)[PAD])pool_s;
    float (*b2_s)[PAD] = (float (*)[PAD])(pool_s + 2560);

    const int tid = threadIdx.x;
    const int b0 = blockIdx.x * RPB;
    const int j = tid & 127, rg = tid >> 7, rbase = rg * 8;

    for (int i = tid; i < RPB * 64; i += 256) {
        int r = i >> 6, k = i & 63;
        inp_s[k][r] = g_ctx[(size_t)(b0 + r) * 64 + k];
    }
    if (tid < 7 * PAD) (&inp_s[89][0])[tid] = 0.f;
    for (int i = tid; i < RPB * 25; i += 256) {
        int r = i / 25, k = i - r * 25;
        int ii = k / 5, jj = k - ii * 5;
        const float* p = C + ((size_t)(b0 + r) * T_LEN + (T_LEN - 1)) * 25;
        inp_s[64 + k][r] = 0.5f * (p[ii * 5 + jj] + p[jj * 5 + ii]);
    }
    __syncthreads();

    ull pc_dr[4], pc_df[4];
    {
        ull bd = pack2f(db0[j]), bf = pack2f(fb0[j]);
#pragma unroll
        for (int p = 0; p < 4; p++) { pc_dr[p] = bd; pc_df[p] = bf; }
#pragma unroll 2
        for (int kb = 0; kb < 8; kb++) {
            uint4 wd4 = ((const uint4*)g_dr0C)[kb * 128 + j];
            uint4 wf4 = ((const uint4*)g_df0C)[kb * 128 + j];
            int k = kb * 8;
            CTX_PAIR(wd4.x, wf4.x, k);
            CTX_PAIR(wd4.y, wf4.y, k + 2);
            CTX_PAIR(wd4.z, wf4.z, k + 4);
            CTX_PAIR(wd4.w, wf4.w, k + 6);
        }
    }

    const float v_db1 = db1[j], v_db2 = db2[j];
    const float v_fb1 = fb1[j];

    for (int step = 0; step < NSTEPS; step++) {
        mlp_layer0(g_dr0D, inp_s, b1_s, pc_dr, j, rbase);
        __syncthreads();
        mlp_layer64(g_dr1P, b1_s, b2_s, v_db1, j, rbase);
        __syncthreads();
        mlp_layer64(g_dr2P, b2_s, b1_s, v_db2, j, rbase);
        __syncthreads();
        {
            if (tid < 240) {
                int r = tid / 15, k = tid - r * 15;
                float acc = db3[k];
#pragma unroll 4
                for (int cc = 0; cc < 128; cc++) acc += b1_s[cc][r] * g_dr3T[cc * 15 + k];
                inp_s[90 + k][r] = acc;
            }
            mlp_layer0(g_df0D, inp_s, b2_s, pc_df, j, rbase);
        }
        __syncthreads();
        mlp_layer64(g_df1P, b2_s, b1_s, v_fb1, j, rbase);
        __syncthreads();
        if (tid < 240) {
            int r = tid / 15, k = tid - r * 15;
            float acc = fb2[k];
#pragma unroll 4
            for (int cc = 0; cc < 128; cc++) acc += b1_s[cc][r] * g_df2T[cc * 15 + k];
            float sp = (acc > 20.f) ? acc : log1pf(__expf(acc));
            float dwv = dW[((size_t)(b0 + r) * NSTEPS + step) * DDIM + k];
            inp_s[90 + k][r] = inp_s[90 + k][r] * DT_C + sp * dwv;
        }
        __syncthreads();
        if (tid < RPB) geo_update(&inp_s[0][tid]);
        __syncthreads();
    }

    for (int i = tid; i < RPB * 25; i += 256) {
        int r = i / 25, k = i - r * 25;
        out[(size_t)(b0 + r) * 25 + k] = inp_s[64 + k][r];
    }
}

// ---------------- launch ---------------------------------------------------------
extern "C" void kernel_launch(void* const* d_in, const int* in_sizes, int n_in,
                              void* d_out, int out_size) {
    const float* ctx_spd = (const float*)d_in[0];
    const float* dWp     = (const float*)d_in[1];
    const float* wih     = (const float*)d_in[2];
    const float* whh     = (const float*)d_in[3];
    const float* gbias   = (const float*)d_in[4];
    const float* gbias_n = (const float*)d_in[5];
    const float* projw   = (const float*)d_in[6];
    const float* projb   = (const float*)d_in[7];
    const float* dw0 = (const float*)d_in[8];  const float* db0 = (const float*)d_in[9];
    const float* dw1 = (const float*)d_in[10]; const float* db1 = (const float*)d_in[11];
    const float* dw2 = (const float*)d_in[12]; const float* db2 = (const float*)d_in[13];
    const float* dw3 = (const float*)d_in[14]; const float* db3 = (const float*)d_in[15];
    const float* fw0 = (const float*)d_in[16]; const float* fb0 = (const float*)d_in[17];
    const float* fw1 = (const float*)d_in[18]; const float* fb1 = (const float*)d_in[19];
    const float* fw2 = (const float*)d_in[20]; const float* fb2 = (const float*)d_in[21];
    float* out = (float*)d_out;

    static int smem_set = 0;
    if (!smem_set) {
        cudaFuncSetAttribute(gru_mma_kernel, cudaFuncAttributeMaxDynamicSharedMemorySize, GRU_SMEM);
        smem_set = 1;
    }

    prep_kernel<<<64, 256>>>(wih, whh, projw, dw0, dw1, dw2, dw3, fw0, fw1, fw2);
    gru_mma_kernel<<<GRU_NBLK, 256, GRU_SMEM>>>(ctx_spd, gbias, gbias_n, projb);
    sde_kernel<<<NBLK, 256>>>(ctx_spd, dWp, db0, db1, db2, db3, fb0, fb1, fb2, out);
}